// round 16
// baseline (speedup 1.0000x reference)
#include <cuda_runtime.h>
#include <cuda_bf16.h>
#include <cstdint>
#include <math.h>
#include <mma.h>

using namespace nvcuda;

#define NN 100000
#define EE 150000
#define DD 512
#define HH 8

#define GBM 128
#define GBN 128
#define GBK 32
#define APADE 8
#define BPADE 8

// ---------------- scratch ---------------------------------------------------
__device__ __nv_bfloat16 g_hb_o[(size_t)NN * DD];
__device__ __nv_bfloat16 g_hb_e[(size_t)NN * DD];
__device__ __nv_bfloat16 g_Ab[(size_t)NN * DD];
__device__ __nv_bfloat16 g_Ab2[(size_t)NN * DD];
__device__ __nv_bfloat16 g_Agg[(size_t)2 * NN * DD];
__device__ __nv_bfloat16 g_Wb0[DD * DD];
__device__ __nv_bfloat16 g_Wb1[DD * DD];
__device__ __nv_bfloat16 g_Wb2[DD * DD];
__device__ float g_a_se[NN * HH];
__device__ float g_a_de[NN * HH];
__device__ float g_a_so[NN * HH];
__device__ float g_a_do[NN * HH];
__device__ unsigned g_amax[2 * NN * HH];
__device__ float g_denom[2 * NN * HH];
__device__ float g_ebuf[2 * EE * HH];
__device__ int g_deg[2 * NN];
__device__ int g_cur[2 * NN];
__device__ int g_startArr[2 * NN];
__device__ int g_ind[2 * NN];
__device__ int g_nzpos[2 * NN];
__device__ int g_bsum[256];
__device__ int g_bsum2[256];
__device__ int g_meta[4];     // {nz0, P0, M1, NN-nz1}
__device__ int g_eidx[2 * EE];
__device__ int g_esrc[2 * EE];
__device__ float g_ksum[2 * DD];
__device__ float g_musum[2 * DD];

// ---------------- helpers ---------------------------------------------------
__device__ __forceinline__ unsigned mapf(float f) {
    unsigned u = __float_as_uint(f);
    return (u & 0x80000000u) ? ~u : (u | 0x80000000u);
}
__device__ __forceinline__ float unmapf(unsigned u) {
    return __uint_as_float((u & 0x80000000u) ? (u & 0x7FFFFFFFu) : ~u);
}
__device__ __forceinline__ float tanha(float x) {
    float r;
    asm("tanh.approx.f32 %0, %1;" : "=f"(r) : "f"(x));
    return r;
}

__global__ void zero_buf(float* p, long n) {
    long i = (long)blockIdx.x * blockDim.x + threadIdx.x;
    long stride = (long)gridDim.x * blockDim.x;
    for (; i < n; i += stride) p[i] = 0.0f;
}

__global__ void init_edge_state2(unsigned* amax, float* denom, int* deg,
                                 int* cur, int n) {
    int i = blockIdx.x * blockDim.x + threadIdx.x;
    if (i < n) { amax[i] = 0x007FFFFFu; denom[i] = 0.0f; }
    if (i < 2 * NN) { deg[i] = 0; cur[i] = 0; }
}

// ---------------- fp32 -> bf16 ----------------------------------------------
__global__ void conv_bf(const float* __restrict__ src,
                        __nv_bfloat16* __restrict__ dst, long n) {
    long i = ((long)blockIdx.x * blockDim.x + threadIdx.x) * 4;
    long stride = (long)gridDim.x * blockDim.x * 4;
    for (; i < n; i += stride) {
        float4 v = *(const float4*)(src + i);
        *(__nv_bfloat162*)(dst + i)     = __floats2bfloat162_rn(v.x, v.y);
        *(__nv_bfloat162*)(dst + i + 2) = __floats2bfloat162_rn(v.z, v.w);
    }
}

// ---------------- column sums of compacted Agg -------------------------------
__global__ void mu_bf2(const __nv_bfloat16* __restrict__ a,
                       float* __restrict__ musum, const int* __restrict__ meta) {
    int f = threadIdx.x;
    int P0 = meta[1], M1 = meta[2];
    int chunk = (2 * NN + gridDim.x - 1) / gridDim.x;
    int r0 = blockIdx.x * chunk;
    int r1 = min(M1, r0 + chunk);
    float acc0 = 0.f, acc1 = 0.f;
    for (int r = r0; r < r1; r++) {
        float v = __bfloat162float(a[(size_t)r * DD + f]);
        if (r < P0) acc0 += v; else acc1 += v;
    }
    if (acc0 != 0.f) atomicAdd(&musum[f], acc0);
    if (acc1 != 0.f) atomicAdd(&musum[DD + f], acc1);
}

// ---------------- BF16 TC GEMM, 2-stage cp.async -----------------------------
template <int MODE>
__global__ void __launch_bounds__(256) gemm_bf(
        const __nv_bfloat16* __restrict__ A, const __nv_bfloat16* __restrict__ W,
        const float* __restrict__ bias, void* __restrict__ Cv, int M,
        float* __restrict__ ksum_out, const int* __restrict__ meta) {
    __shared__ __nv_bfloat16 As[2][GBM][GBK + APADE];
    __shared__ __nv_bfloat16 Bs[2][GBK][GBN + BPADE];
    __shared__ float stage[8][16][20];
    __shared__ float ksred[GBN];

    int m0 = blockIdx.y * GBM;
    int bank = 0;
    if (MODE == 1) {
        int Mv = meta[2];
        if (m0 >= Mv) return;
        M = Mv;
        bank = (m0 >= meta[1]) ? 1 : 0;
    }

    int tid = threadIdx.x;
    int wid = tid >> 5;
    int lane = tid & 31;
    int warp_m = wid & 3;
    int warp_n = wid >> 2;
    int n0 = blockIdx.x * GBN;
    int wm0 = warp_m * 32;
    int wn0 = warp_n * 64;

    if (MODE == 1 && tid < GBN) ksred[tid] = 0.0f;

    auto load_stage = [&](int s, int k0) {
#pragma unroll
        for (int it = 0; it < 2; it++) {
            int idx = tid + it * 256;
            int ar = idx >> 2, ac = (idx & 3) * 8;
            int gm = m0 + ar;
            const __nv_bfloat16* srcA =
                A + (size_t)(gm < M ? gm : M - 1) * DD + k0 + ac;
            uint32_t dstA = (uint32_t)__cvta_generic_to_shared(&As[s][ar][ac]);
            asm volatile("cp.async.cg.shared.global [%0], [%1], 16, 16;"
                         :: "r"(dstA), "l"(srcA));
            int br = idx >> 4, bc = (idx & 15) * 8;
            const __nv_bfloat16* srcB = W + (size_t)(k0 + br) * DD + n0 + bc;
            uint32_t dstB = (uint32_t)__cvta_generic_to_shared(&Bs[s][br][bc]);
            asm volatile("cp.async.cg.shared.global [%0], [%1], 16, 16;"
                         :: "r"(dstB), "l"(srcB));
        }
        asm volatile("cp.async.commit_group;");
    };

    wmma::fragment<wmma::accumulator, 16, 16, 16, float> acc[2][4];
#pragma unroll
    for (int i = 0; i < 2; i++)
#pragma unroll
        for (int j = 0; j < 4; j++) wmma::fill_fragment(acc[i][j], 0.0f);

    load_stage(0, 0);

    int sbuf = 0;
    for (int k0 = 0; k0 < DD; k0 += GBK) {
        asm volatile("cp.async.wait_group 0;" ::: "memory");
        __syncthreads();
        if (k0 + GBK < DD) load_stage(sbuf ^ 1, k0 + GBK);

#pragma unroll
        for (int kk = 0; kk < GBK; kk += 16) {
            wmma::fragment<wmma::matrix_a, 16, 16, 16, __nv_bfloat16,
                           wmma::row_major> af[2];
            wmma::fragment<wmma::matrix_b, 16, 16, 16, __nv_bfloat16,
                           wmma::row_major> bf[4];
#pragma unroll
            for (int i = 0; i < 2; i++)
                wmma::load_matrix_sync(af[i], &As[sbuf][wm0 + i * 16][kk],
                                       GBK + APADE);
#pragma unroll
            for (int j = 0; j < 4; j++)
                wmma::load_matrix_sync(bf[j], &Bs[sbuf][kk][wn0 + j * 16],
                                       GBN + BPADE);
#pragma unroll
            for (int i = 0; i < 2; i++)
#pragma unroll
                for (int j = 0; j < 4; j++)
                    wmma::mma_sync(acc[i][j], af[i], bf[j], acc[i][j]);
        }
        sbuf ^= 1;
    }
    __syncthreads();

    int r = lane >> 1;
    int cbase = (lane & 1) * 8;
#pragma unroll
    for (int i = 0; i < 2; i++) {
#pragma unroll
        for (int j = 0; j < 4; j++) {
            wmma::store_matrix_sync(&stage[wid][0][0], acc[i][j], 20,
                                    wmma::mem_row_major);
            __syncwarp();
            int grow = m0 + wm0 + i * 16 + r;
            int gcol = n0 + wn0 + j * 16 + cbase;
            if (MODE == 0) {
                if (grow < M) {
                    float4 v1 = *(const float4*)(&stage[wid][r][cbase]);
                    float4 v2 = *(const float4*)(&stage[wid][r][cbase + 4]);
                    float4 b1 = *(const float4*)(bias + gcol);
                    float4 b2 = *(const float4*)(bias + gcol + 4);
                    v1.x += b1.x; v1.y += b1.y; v1.z += b1.z; v1.w += b1.w;
                    v2.x += b2.x; v2.y += b2.y; v2.z += b2.z; v2.w += b2.w;
                    __nv_bfloat162 r0 = __floats2bfloat162_rn(v1.x, v1.y);
                    __nv_bfloat162 r1 = __floats2bfloat162_rn(v1.z, v1.w);
                    __nv_bfloat162 r2 = __floats2bfloat162_rn(v2.x, v2.y);
                    __nv_bfloat162 r3 = __floats2bfloat162_rn(v2.z, v2.w);
                    uint4 ov;
                    ov.x = *reinterpret_cast<unsigned*>(&r0);
                    ov.y = *reinterpret_cast<unsigned*>(&r1);
                    ov.z = *reinterpret_cast<unsigned*>(&r2);
                    ov.w = *reinterpret_cast<unsigned*>(&r3);
                    *(uint4*)((__nv_bfloat16*)Cv + (size_t)grow * DD + gcol) = ov;
                }
            } else {
                float t[8];
                if (grow < M) {
                    float4 v1 = *(const float4*)(&stage[wid][r][cbase]);
                    float4 v2 = *(const float4*)(&stage[wid][r][cbase + 4]);
                    float4 b1 = *(const float4*)(bias + gcol);
                    float4 b2 = *(const float4*)(bias + gcol + 4);
                    t[0] = tanha(v1.x + b1.x); t[1] = tanha(v1.y + b1.y);
                    t[2] = tanha(v1.z + b1.z); t[3] = tanha(v1.w + b1.w);
                    t[4] = tanha(v2.x + b2.x); t[5] = tanha(v2.y + b2.y);
                    t[6] = tanha(v2.z + b2.z); t[7] = tanha(v2.w + b2.w);
                } else {
#pragma unroll
                    for (int q = 0; q < 8; q++) t[q] = 0.f;
                }
#pragma unroll
                for (int d = 2; d <= 16; d <<= 1)
#pragma unroll
                    for (int q = 0; q < 8; q++)
                        t[q] += __shfl_xor_sync(0xffffffffu, t[q], d);
                if (lane < 2) {
                    int lc = wn0 + j * 16 + lane * 8;
#pragma unroll
                    for (int q = 0; q < 8; q++)
                        atomicAdd(&ksred[lc + q], t[q]);
                }
            }
            __syncwarp();
        }
    }
    if (MODE == 1) {
        __syncthreads();
        if (tid < GBN)
            atomicAdd(&ksum_out[bank * DD + n0 + tid], ksred[tid]);
    }
}

// ---------------- attention dots from bf16 h --------------------------------
__global__ void compute_ah3(const __nv_bfloat16* __restrict__ hmat,
                            const float* __restrict__ att0, float* __restrict__ a0,
                            const float* __restrict__ att1, float* __restrict__ a1,
                            const float* __restrict__ att2, float* __restrict__ a2,
                            int n_nodes) {
    int gt = blockIdx.x * blockDim.x + threadIdx.x;
    int warp = gt >> 5;
    int lane = threadIdx.x & 31;
    if (warp >= n_nodes) return;
    int base = lane * 16;
    const uint4* hp = (const uint4*)(hmat + (size_t)warp * DD + base);
    uint4 qa = hp[0], qb = hp[1];
    __nv_bfloat162* pa = reinterpret_cast<__nv_bfloat162*>(&qa);
    __nv_bfloat162* pb = reinterpret_cast<__nv_bfloat162*>(&qb);
    float hv[16];
#pragma unroll
    for (int j = 0; j < 4; j++) {
        float2 f = __bfloat1622float2(pa[j]);
        hv[2 * j] = f.x; hv[2 * j + 1] = f.y;
        float2 g = __bfloat1622float2(pb[j]);
        hv[8 + 2 * j] = g.x; hv[8 + 2 * j + 1] = g.y;
    }
    float s0 = 0.f, s1 = 0.f, s2 = 0.f;
    const float4* ap0 = (const float4*)(att0 + base);
    const float4* ap1 = att1 ? (const float4*)(att1 + base) : nullptr;
    const float4* ap2 = att2 ? (const float4*)(att2 + base) : nullptr;
#pragma unroll
    for (int q = 0; q < 4; q++) {
        float4 av = ap0[q];
        s0 += hv[q*4]*av.x + hv[q*4+1]*av.y + hv[q*4+2]*av.z + hv[q*4+3]*av.w;
        if (ap1) {
            float4 bv = ap1[q];
            s1 += hv[q*4]*bv.x + hv[q*4+1]*bv.y + hv[q*4+2]*bv.z + hv[q*4+3]*bv.w;
        }
        if (ap2) {
            float4 cv = ap2[q];
            s2 += hv[q*4]*cv.x + hv[q*4+1]*cv.y + hv[q*4+2]*cv.z + hv[q*4+3]*cv.w;
        }
    }
#pragma unroll
    for (int d = 1; d <= 2; d <<= 1) {
        s0 += __shfl_xor_sync(0xffffffffu, s0, d);
        s1 += __shfl_xor_sync(0xffffffffu, s1, d);
        s2 += __shfl_xor_sync(0xffffffffu, s2, d);
    }
    if ((lane & 3) == 0) {
        int o = warp * HH + (lane >> 2);
        a0[o] = s0;
        if (a1) a1[o] = s1;
        if (a2) a2[o] = s2;
    }
}

// ---------------- edge pass 1 ------------------------------------------------
__global__ void edge_alpha_max2(
        const int* __restrict__ s0p, const int* __restrict__ d0p,
        const int* __restrict__ s1p, const int* __restrict__ d1p,
        const float* __restrict__ ase, const float* __restrict__ ade,
        const float* __restrict__ aso, const float* __restrict__ ado,
        float* __restrict__ alpha, unsigned* __restrict__ amax,
        int* __restrict__ deg, int ne) {
    int i = blockIdx.x * blockDim.x + threadIdx.x;
    int half = ne * HH;
    if (i >= 2 * half) return;
    int m = i >= half;
    int li = m ? i - half : i;
    int e = li >> 3, h = li & 7;
    const int* sp = m ? s1p : s0p;
    const int* dp = m ? d1p : d0p;
    const float* as = m ? aso : ase;
    const float* ad = m ? ado : ade;
    int d = dp[e];
    float v = as[sp[e] * HH + h] + ad[d * HH + h];
    v = (v > 0.f) ? v : 0.2f * v;
    alpha[i] = v;
    atomicMax(&amax[m * NN * HH + d * HH + h], mapf(v));
    if (h == 0) atomicAdd(&deg[m * NN + d], 1);
}

// ---------------- edge pass 2 ------------------------------------------------
__global__ void edge_exp_sum2(
        const int* __restrict__ d0p, const int* __restrict__ d1p,
        float* __restrict__ alpha, const unsigned* __restrict__ amax,
        float* __restrict__ denom, int ne) {
    int i = blockIdx.x * blockDim.x + threadIdx.x;
    int half = ne * HH;
    if (i >= 2 * half) return;
    int m = i >= half;
    int li = m ? i - half : i;
    int e = li >> 3, h = li & 7;
    const int* dp = m ? d1p : d0p;
    int off = m * NN * HH + dp[e] * HH + h;
    float ex = expf(alpha[i] - unmapf(amax[off]));
    alpha[i] = ex;
    atomicAdd(&denom[off], ex);
}

// ---------------- scans -------------------------------------------------------
__global__ void scan1(const int* __restrict__ vin, int* __restrict__ outv,
                      int* __restrict__ bsum, int n) {
    __shared__ int sh[1024];
    int gid = blockIdx.x * 1024 + threadIdx.x;
    int v = (gid < n) ? vin[gid] : 0;
    sh[threadIdx.x] = v;
    __syncthreads();
    for (int off = 1; off < 1024; off <<= 1) {
        int t = (threadIdx.x >= off) ? sh[threadIdx.x - off] : 0;
        __syncthreads();
        sh[threadIdx.x] += t;
        __syncthreads();
    }
    if (gid < n) outv[gid] = sh[threadIdx.x] - v;
    if (threadIdx.x == 1023) bsum[blockIdx.x] = sh[1023];
}

__global__ void scan2(int* __restrict__ bsum, int nb) {
    __shared__ int sh[256];
    int v = (threadIdx.x < nb) ? bsum[threadIdx.x] : 0;
    sh[threadIdx.x] = v;
    __syncthreads();
    for (int off = 1; off < 256; off <<= 1) {
        int t = (threadIdx.x >= off) ? sh[threadIdx.x - off] : 0;
        __syncthreads();
        sh[threadIdx.x] += t;
        __syncthreads();
    }
    if (threadIdx.x < nb) bsum[threadIdx.x] = sh[threadIdx.x] - v;
}

__global__ void scan3(int* __restrict__ outv, const int* __restrict__ bsum,
                      int n) {
    int gid = blockIdx.x * 1024 + threadIdx.x;
    if (gid < n) outv[gid] += bsum[blockIdx.x];
}

__global__ void make_ind(const int* __restrict__ deg, int* __restrict__ ind,
                         int n) {
    int i = blockIdx.x * blockDim.x + threadIdx.x;
    if (i < n) ind[i] = (deg[i] > 0) ? 1 : 0;
}

__global__ void meta_k(const int* __restrict__ nzpos,
                       const int* __restrict__ deg, int* __restrict__ meta) {
    int nz0 = nzpos[NN];
    int nztot = nzpos[2 * NN - 1] + ((deg[2 * NN - 1] > 0) ? 1 : 0);
    int P0 = (nz0 + 127) & ~127;
    int nz1 = nztot - nz0;
    meta[0] = nz0;
    meta[1] = P0;
    meta[2] = P0 + nz1;
    meta[3] = NN - nz1;
}

__global__ void zero_pad(const int* __restrict__ meta,
                         __nv_bfloat16* __restrict__ Agg) {
    int nz0 = meta[0], P0 = meta[1];
    long total = (long)(P0 - nz0) * DD;
    long base = (size_t)nz0 * DD;
    for (long t = (long)blockIdx.x * blockDim.x + threadIdx.x; t < total;
         t += (long)gridDim.x * blockDim.x)
        Agg[base + t] = __float2bfloat16(0.f);
}

__global__ void csr_fill(
        const int* __restrict__ s0p, const int* __restrict__ d0p,
        const int* __restrict__ s1p, const int* __restrict__ d1p,
        const int* __restrict__ startv, int* __restrict__ cur,
        int* __restrict__ eidx, int* __restrict__ esrc, int ne) {
    int i = blockIdx.x * blockDim.x + threadIdx.x;
    if (i >= 2 * ne) return;
    int m = i >= ne;
    int le = m ? i - ne : i;
    int d = m ? d1p[le] : d0p[le];
    int s = m ? s1p[le] : s0p[le];
    int dd = m * NN + d;
    int pos = startv[dd] + atomicAdd(&cur[dd], 1);
    eidx[pos] = i;
    esrc[pos] = s;
}

// ---------------- gather -> compacted Agg ------------------------------------
__global__ void gather_conv(
        const int* __restrict__ eidx, const int* __restrict__ esrc,
        const int* __restrict__ startv, const int* __restrict__ deg,
        const int* __restrict__ nzpos, const int* __restrict__ meta,
        const __nv_bfloat16* __restrict__ h0,
        const __nv_bfloat16* __restrict__ h1,
        const float* __restrict__ ebuf, const float* __restrict__ denom,
        __nv_bfloat16* __restrict__ Agg) {
    int gw = (blockIdx.x * blockDim.x + threadIdx.x) >> 5;
    int lane = threadIdx.x & 31;
    if (gw >= 2 * NN) return;
    int de = deg[gw];
    if (de == 0) return;
    int m = gw >= NN;
    const __nv_bfloat16* hs = m ? h1 : h0;
    int row = m ? (meta[1] + nzpos[gw] - meta[0]) : nzpos[gw];
    int st = startv[gw];
    int h = lane >> 2;
    float dinv = 1.0f / (denom[gw * HH + h] + 1e-16f);
    float acc[16];
#pragma unroll
    for (int q = 0; q < 16; q++) acc[q] = 0.f;

    for (int p = 0; p < de; p++) {
        int ge = eidx[st + p];
        int s  = esrc[st + p];
        float w = ebuf[ge * HH + h] * dinv;
        const uint4* hp = (const uint4*)(hs + (size_t)s * DD + lane * 16);
        uint4 qa = hp[0], qb = hp[1];
        __nv_bfloat162* pa = reinterpret_cast<__nv_bfloat162*>(&qa);
        __nv_bfloat162* pb = reinterpret_cast<__nv_bfloat162*>(&qb);
#pragma unroll
        for (int j = 0; j < 4; j++) {
            float2 f = __bfloat1622float2(pa[j]);
            acc[2 * j]     += f.x * w;
            acc[2 * j + 1] += f.y * w;
            float2 g = __bfloat1622float2(pb[j]);
            acc[8 + 2 * j]     += g.x * w;
            acc[8 + 2 * j + 1] += g.y * w;
        }
    }

    uint4 o1, o2;
#pragma unroll
    for (int j = 0; j < 8; j++) {
        float a = fmaxf(acc[2 * j], 0.f);
        float b = fmaxf(acc[2 * j + 1], 0.f);
        __nv_bfloat162 pk = __floats2bfloat162_rn(a, b);
        if (j < 4) (&o1.x)[j] = *reinterpret_cast<unsigned*>(&pk);
        else       (&o2.x)[j - 4] = *reinterpret_cast<unsigned*>(&pk);
    }
    uint4* dst = (uint4*)(Agg + (size_t)row * DD + lane * 16);
    dst[0] = o1;
    dst[1] = o2;
}

// ---------------- final -------------------------------------------------------
__global__ void final_kernel(const float* __restrict__ qsem,
                             const float* __restrict__ klb,
                             const float* __restrict__ linw,
                             const float* __restrict__ linb,
                             const int* __restrict__ meta,
                             float* __restrict__ out) {
    __shared__ float sh[DD];
    __shared__ float sv[2];
    int f = threadIdx.x;
    const float invN = 1.0f / (float)NN;
    float q = qsem[f];
    float tb = tanhf(klb[f]);
    float c0 = (float)(NN - meta[1]);
    float c1 = (float)meta[3];
    float v0 = (g_ksum[f] + c0 * tb) * invN * q;
    float v1 = (g_ksum[DD + f] + c1 * tb) * invN * q;

    sh[f] = v0; __syncthreads();
    for (int s = 256; s > 0; s >>= 1) { if (f < s) sh[f] += sh[f + s]; __syncthreads(); }
    if (f == 0) sv[0] = sh[0];
    __syncthreads();
    sh[f] = v1; __syncthreads();
    for (int s = 256; s > 0; s >>= 1) { if (f < s) sh[f] += sh[f + s]; __syncthreads(); }
    if (f == 0) sv[1] = sh[0];
    __syncthreads();

    float s0 = sv[0], s1 = sv[1];
    float mx = fmaxf(s0, s1);
    float e0 = expf(s0 - mx), e1 = expf(s1 - mx);
    float sem0 = e0 / (e0 + e1), sem1 = e1 / (e0 + e1);

    float pooled = (sem0 * g_musum[f] + sem1 * g_musum[DD + f]) * invN;
    float w0 = pooled * linw[f * 2 + 0];
    float w1 = pooled * linw[f * 2 + 1];

    sh[f] = w0; __syncthreads();
    for (int s = 256; s > 0; s >>= 1) { if (f < s) sh[f] += sh[f + s]; __syncthreads(); }
    if (f == 0) out[0] = sh[0] + linb[0];
    __syncthreads();
    sh[f] = w1; __syncthreads();
    for (int s = 256; s > 0; s >>= 1) { if (f < s) sh[f] += sh[f + s]; __syncthreads(); }
    if (f == 0) out[1] = sh[0] + linb[1];
}

// ---------------- host launcher ---------------------------------------------
extern "C" void kernel_launch(void* const* d_in, const int* in_sizes, int n_in,
                              void* d_out, int out_size) {
    const float* x_o  = (const float*)d_in[0];
    const float* x_e  = (const float*)d_in[1];
    const int*   e2o  = (const int*)d_in[2];
    const int*   o2o  = (const int*)d_in[3];
    const float* powm = (const float*)d_in[4];
    const float* pob  = (const float*)d_in[5];
    const float* pewm = (const float*)d_in[6];
    const float* peb  = (const float*)d_in[7];
    const float* a_s_e2o = (const float*)d_in[8];
    const float* a_d_e2o = (const float*)d_in[9];
    const float* a_s_o2o = (const float*)d_in[10];
    const float* a_d_o2o = (const float*)d_in[11];
    const float* klw  = (const float*)d_in[12];
    const float* klb  = (const float*)d_in[13];
    const float* qsem = (const float*)d_in[14];
    const float* linw = (const float*)d_in[15];
    const float* linb = (const float*)d_in[16];
    float* out = (float*)d_out;

    void* p;
    float *a_se, *a_de, *a_so, *a_do, *denom, *ebuf, *ksum, *musum;
    __nv_bfloat16 *hb_o, *hb_e, *Ab, *Ab2, *Agg, *Wb0, *Wb1, *Wb2;
    unsigned* amax;
    int *deg, *cur, *startv, *ind, *nzpos, *bsum, *bsum2, *meta, *eidx, *esrc;
    cudaGetSymbolAddress(&p, g_hb_o); hb_o = (__nv_bfloat16*)p;
    cudaGetSymbolAddress(&p, g_hb_e); hb_e = (__nv_bfloat16*)p;
    cudaGetSymbolAddress(&p, g_Ab);   Ab   = (__nv_bfloat16*)p;
    cudaGetSymbolAddress(&p, g_Ab2);  Ab2  = (__nv_bfloat16*)p;
    cudaGetSymbolAddress(&p, g_Agg);  Agg  = (__nv_bfloat16*)p;
    cudaGetSymbolAddress(&p, g_Wb0);  Wb0  = (__nv_bfloat16*)p;
    cudaGetSymbolAddress(&p, g_Wb1);  Wb1  = (__nv_bfloat16*)p;
    cudaGetSymbolAddress(&p, g_Wb2);  Wb2  = (__nv_bfloat16*)p;
    cudaGetSymbolAddress(&p, g_a_se); a_se = (float*)p;
    cudaGetSymbolAddress(&p, g_a_de); a_de = (float*)p;
    cudaGetSymbolAddress(&p, g_a_so); a_so = (float*)p;
    cudaGetSymbolAddress(&p, g_a_do); a_do = (float*)p;
    cudaGetSymbolAddress(&p, g_amax); amax = (unsigned*)p;
    cudaGetSymbolAddress(&p, g_denom); denom = (float*)p;
    cudaGetSymbolAddress(&p, g_ebuf); ebuf = (float*)p;
    cudaGetSymbolAddress(&p, g_deg);  deg  = (int*)p;
    cudaGetSymbolAddress(&p, g_cur);  cur  = (int*)p;
    cudaGetSymbolAddress(&p, g_startArr); startv = (int*)p;
    cudaGetSymbolAddress(&p, g_ind);  ind  = (int*)p;
    cudaGetSymbolAddress(&p, g_nzpos); nzpos = (int*)p;
    cudaGetSymbolAddress(&p, g_bsum); bsum = (int*)p;
    cudaGetSymbolAddress(&p, g_bsum2); bsum2 = (int*)p;
    cudaGetSymbolAddress(&p, g_meta); meta = (int*)p;
    cudaGetSymbolAddress(&p, g_eidx); eidx = (int*)p;
    cudaGetSymbolAddress(&p, g_esrc); esrc = (int*)p;
    cudaGetSymbolAddress(&p, g_ksum); ksum = (float*)p;
    cudaGetSymbolAddress(&p, g_musum); musum = (float*)p;

    const long ND = (long)NN * DD;
    dim3 tcgrid(DD / GBN, (NN + GBM - 1) / GBM);
    dim3 tcgrid2(DD / GBN, (2 * NN + GBM - 1) / GBM);
    const int NTOT = 2 * NN;
    const int SCAN_BLOCKS = (NTOT + 1023) / 1024;

    int ah_blocks = (NN * 32 + 255) / 256;
    int e2_blocks = (2 * EE * HH + 255) / 256;
    int ef_blocks = (2 * EE + 255) / 256;
    int ie_blocks = (2 * NN * HH + 255) / 256;
    int gw_blocks = (2 * NN * 32 + 255) / 256;

    // ---- streams + events (host resources only; created/destroyed per call) --
    cudaStream_t st1, st2;
    cudaStreamCreateWithFlags(&st1, cudaStreamNonBlocking);
    cudaStreamCreateWithFlags(&st2, cudaStreamNonBlocking);
    cudaEvent_t eF, e1, e2, e3, e4, e5, e6;
    cudaEventCreateWithFlags(&eF, cudaEventDisableTiming);
    cudaEventCreateWithFlags(&e1, cudaEventDisableTiming);
    cudaEventCreateWithFlags(&e2, cudaEventDisableTiming);
    cudaEventCreateWithFlags(&e3, cudaEventDisableTiming);
    cudaEventCreateWithFlags(&e4, cudaEventDisableTiming);
    cudaEventCreateWithFlags(&e5, cudaEventDisableTiming);
    cudaEventCreateWithFlags(&e6, cudaEventDisableTiming);

    // ---- fork ----
    cudaEventRecord(eF, 0);
    cudaStreamWaitEvent(st1, eF, 0);
    cudaStreamWaitEvent(st2, eF, 0);

    // main: path A (x_o)
    conv_bf<<<256, 256>>>(powm, Wb0, DD * DD);
    conv_bf<<<2048, 256>>>(x_o, Ab, ND);
    gemm_bf<0><<<tcgrid, 256>>>(Ab, Wb0, pob, hb_o, NN, nullptr, nullptr);
    compute_ah3<<<ah_blocks, 256>>>(hb_o, a_d_e2o, a_de, a_s_o2o, a_so,
                                    a_d_o2o, a_do, NN);

    // st1: path B (x_e)
    conv_bf<<<256, 256, 0, st1>>>(pewm, Wb1, DD * DD);
    conv_bf<<<2048, 256, 0, st1>>>(x_e, Ab2, ND);
    gemm_bf<0><<<tcgrid, 256, 0, st1>>>(Ab2, Wb1, peb, hb_e, NN, nullptr, nullptr);
    compute_ah3<<<ah_blocks, 256, 0, st1>>>(hb_e, a_s_e2o, a_se,
                                            nullptr, nullptr, nullptr, nullptr, NN);

    // st2: independent prep
    zero_buf<<<4, 256, 0, st2>>>(ksum, 2 * DD);
    zero_buf<<<4, 256, 0, st2>>>(musum, 2 * DD);
    conv_bf<<<256, 256, 0, st2>>>(klw, Wb2, DD * DD);
    init_edge_state2<<<ie_blocks, 256, 0, st2>>>(amax, denom, deg, cur, 2 * NN * HH);

    // ---- join st1, st2 ----
    cudaEventRecord(e1, st1); cudaStreamWaitEvent(0, e1, 0);
    cudaEventRecord(e2, st2); cudaStreamWaitEvent(0, e2, 0);

    // edge pass 1 (produces alpha, amax, deg)
    edge_alpha_max2<<<e2_blocks, 256>>>(e2o, e2o + EE, o2o, o2o + EE,
                                        a_se, a_de, a_so, a_do, ebuf, amax, deg, EE);

    // fork: compaction chain on st1, softmax+CSR chain on main
    cudaEventRecord(e3, 0);
    cudaStreamWaitEvent(st1, e3, 0);
    make_ind<<<(NTOT + 255) / 256, 256, 0, st1>>>(deg, ind, NTOT);
    scan1<<<SCAN_BLOCKS, 1024, 0, st1>>>(ind, nzpos, bsum2, NTOT);
    scan2<<<1, 256, 0, st1>>>(bsum2, SCAN_BLOCKS);
    scan3<<<SCAN_BLOCKS, 1024, 0, st1>>>(nzpos, bsum2, NTOT);
    meta_k<<<1, 1, 0, st1>>>(nzpos, deg, meta);
    zero_pad<<<128, 256, 0, st1>>>(meta, Agg);

    edge_exp_sum2<<<e2_blocks, 256>>>(e2o + EE, o2o + EE, ebuf, amax, denom, EE);
    scan1<<<SCAN_BLOCKS, 1024>>>(deg, startv, bsum, NTOT);
    scan2<<<1, 256>>>(bsum, SCAN_BLOCKS);
    scan3<<<SCAN_BLOCKS, 1024>>>(startv, bsum, NTOT);
    csr_fill<<<ef_blocks, 256>>>(e2o, e2o + EE, o2o, o2o + EE,
                                 startv, cur, eidx, esrc, EE);

    // join compaction chain
    cudaEventRecord(e4, st1); cudaStreamWaitEvent(0, e4, 0);

    // gather -> compacted Agg
    gather_conv<<<gw_blocks, 256>>>(eidx, esrc, startv, deg, nzpos, meta,
                                    hb_e, hb_o, ebuf, denom, Agg);

    // fork: mu on st1 concurrent with MODE-1 GEMM on main
    cudaEventRecord(e5, 0);
    cudaStreamWaitEvent(st1, e5, 0);
    mu_bf2<<<256, 512, 0, st1>>>(Agg, musum, meta);
    gemm_bf<1><<<tcgrid2, 256>>>(Agg, Wb2, klb, nullptr, 2 * NN, ksum, meta);
    cudaEventRecord(e6, st1); cudaStreamWaitEvent(0, e6, 0);

    // final
    final_kernel<<<1, 512>>>(qsem, klb, linw, linb, meta, out);

    cudaEventDestroy(eF); cudaEventDestroy(e1); cudaEventDestroy(e2);
    cudaEventDestroy(e3); cudaEventDestroy(e4); cudaEventDestroy(e5);
    cudaEventDestroy(e6);
    cudaStreamDestroy(st1);
    cudaStreamDestroy(st2);
}

// round 17
// speedup vs baseline: 1.4190x; 1.4190x over previous
#include <cuda_runtime.h>
#include <cuda_bf16.h>
#include <cstdint>
#include <math.h>
#include <mma.h>

using namespace nvcuda;

#define NN 100000
#define EE 150000
#define DD 512
#define HH 8

#define GBM 128
#define GBN 128
#define GBK 32
#define APADE 8
#define BPADE 8

// ---------------- scratch ---------------------------------------------------
__device__ __nv_bfloat16 g_hb_o[(size_t)NN * DD];
__device__ __nv_bfloat16 g_hb_e[(size_t)NN * DD];
__device__ __nv_bfloat16 g_Ab[(size_t)NN * DD];
__device__ __nv_bfloat16 g_Agg[(size_t)2 * NN * DD];
__device__ __nv_bfloat16 g_Wb[DD * DD];
__device__ float g_a_se[NN * HH];
__device__ float g_a_de[NN * HH];
__device__ float g_a_so[NN * HH];
__device__ float g_a_do[NN * HH];
__device__ unsigned g_amax[2 * NN * HH];
__device__ float g_denom[2 * NN * HH];
__device__ float g_ebuf[2 * EE * HH];
__device__ int g_deg[2 * NN];
__device__ int g_cur[2 * NN];
__device__ int g_startArr[2 * NN];
__device__ int g_ind[2 * NN];
__device__ int g_nzpos[2 * NN];
__device__ int g_bsum[256];
__device__ int g_bsum2[256];
__device__ int g_meta[4];     // {nz0, P0, M1, NN-nz1}
__device__ int g_eidx[2 * EE];
__device__ int g_esrc[2 * EE];
__device__ float g_ksum[2 * DD];
__device__ float g_musum[2 * DD];

// ---------------- helpers ---------------------------------------------------
__device__ __forceinline__ unsigned mapf(float f) {
    unsigned u = __float_as_uint(f);
    return (u & 0x80000000u) ? ~u : (u | 0x80000000u);
}
__device__ __forceinline__ float unmapf(unsigned u) {
    return __uint_as_float((u & 0x80000000u) ? (u & 0x7FFFFFFFu) : ~u);
}
__device__ __forceinline__ float tanha(float x) {
    float r;
    asm("tanh.approx.f32 %0, %1;" : "=f"(r) : "f"(x));
    return r;
}

__global__ void zero_buf(float* p, long n) {
    long i = (long)blockIdx.x * blockDim.x + threadIdx.x;
    long stride = (long)gridDim.x * blockDim.x;
    for (; i < n; i += stride) p[i] = 0.0f;
}

__global__ void init_edge_state2(unsigned* amax, float* denom, int* deg,
                                 int* cur, int n) {
    int i = blockIdx.x * blockDim.x + threadIdx.x;
    if (i < n) { amax[i] = 0x007FFFFFu; denom[i] = 0.0f; }
    if (i < 2 * NN) { deg[i] = 0; cur[i] = 0; }
}

// ---------------- fp32 -> bf16 ----------------------------------------------
__global__ void conv_bf(const float* __restrict__ src,
                        __nv_bfloat16* __restrict__ dst, long n) {
    long i = ((long)blockIdx.x * blockDim.x + threadIdx.x) * 4;
    long stride = (long)gridDim.x * blockDim.x * 4;
    for (; i < n; i += stride) {
        float4 v = *(const float4*)(src + i);
        *(__nv_bfloat162*)(dst + i)     = __floats2bfloat162_rn(v.x, v.y);
        *(__nv_bfloat162*)(dst + i + 2) = __floats2bfloat162_rn(v.z, v.w);
    }
}

// ---------------- column sums of compacted Agg -------------------------------
__global__ void mu_bf2(const __nv_bfloat16* __restrict__ a,
                       float* __restrict__ musum, const int* __restrict__ meta) {
    int f = threadIdx.x;
    int P0 = meta[1], M1 = meta[2];
    int chunk = (2 * NN + gridDim.x - 1) / gridDim.x;
    int r0 = blockIdx.x * chunk;
    int r1 = min(M1, r0 + chunk);
    float acc0 = 0.f, acc1 = 0.f;
    for (int r = r0; r < r1; r++) {
        float v = __bfloat162float(a[(size_t)r * DD + f]);
        if (r < P0) acc0 += v; else acc1 += v;
    }
    if (acc0 != 0.f) atomicAdd(&musum[f], acc0);
    if (acc1 != 0.f) atomicAdd(&musum[DD + f], acc1);
}

// ---------------- BF16 TC GEMM, 2-stage cp.async -----------------------------
template <int MODE>
__global__ void __launch_bounds__(256) gemm_bf(
        const __nv_bfloat16* __restrict__ A, const __nv_bfloat16* __restrict__ W,
        const float* __restrict__ bias, void* __restrict__ Cv, int M,
        float* __restrict__ ksum_out, const int* __restrict__ meta) {
    __shared__ __nv_bfloat16 As[2][GBM][GBK + APADE];
    __shared__ __nv_bfloat16 Bs[2][GBK][GBN + BPADE];
    __shared__ float stage[8][16][20];
    __shared__ float ksred[GBN];

    int m0 = blockIdx.y * GBM;
    int bank = 0;
    if (MODE == 1) {
        int Mv = meta[2];
        if (m0 >= Mv) return;
        M = Mv;
        bank = (m0 >= meta[1]) ? 1 : 0;
    }

    int tid = threadIdx.x;
    int wid = tid >> 5;
    int lane = tid & 31;
    int warp_m = wid & 3;
    int warp_n = wid >> 2;
    int n0 = blockIdx.x * GBN;
    int wm0 = warp_m * 32;
    int wn0 = warp_n * 64;

    if (MODE == 1 && tid < GBN) ksred[tid] = 0.0f;

    auto load_stage = [&](int s, int k0) {
#pragma unroll
        for (int it = 0; it < 2; it++) {
            int idx = tid + it * 256;
            int ar = idx >> 2, ac = (idx & 3) * 8;
            int gm = m0 + ar;
            const __nv_bfloat16* srcA =
                A + (size_t)(gm < M ? gm : M - 1) * DD + k0 + ac;
            uint32_t dstA = (uint32_t)__cvta_generic_to_shared(&As[s][ar][ac]);
            asm volatile("cp.async.cg.shared.global [%0], [%1], 16, 16;"
                         :: "r"(dstA), "l"(srcA));
            int br = idx >> 4, bc = (idx & 15) * 8;
            const __nv_bfloat16* srcB = W + (size_t)(k0 + br) * DD + n0 + bc;
            uint32_t dstB = (uint32_t)__cvta_generic_to_shared(&Bs[s][br][bc]);
            asm volatile("cp.async.cg.shared.global [%0], [%1], 16, 16;"
                         :: "r"(dstB), "l"(srcB));
        }
        asm volatile("cp.async.commit_group;");
    };

    wmma::fragment<wmma::accumulator, 16, 16, 16, float> acc[2][4];
#pragma unroll
    for (int i = 0; i < 2; i++)
#pragma unroll
        for (int j = 0; j < 4; j++) wmma::fill_fragment(acc[i][j], 0.0f);

    load_stage(0, 0);

    int sbuf = 0;
    for (int k0 = 0; k0 < DD; k0 += GBK) {
        asm volatile("cp.async.wait_group 0;" ::: "memory");
        __syncthreads();
        if (k0 + GBK < DD) load_stage(sbuf ^ 1, k0 + GBK);

#pragma unroll
        for (int kk = 0; kk < GBK; kk += 16) {
            wmma::fragment<wmma::matrix_a, 16, 16, 16, __nv_bfloat16,
                           wmma::row_major> af[2];
            wmma::fragment<wmma::matrix_b, 16, 16, 16, __nv_bfloat16,
                           wmma::row_major> bf[4];
#pragma unroll
            for (int i = 0; i < 2; i++)
                wmma::load_matrix_sync(af[i], &As[sbuf][wm0 + i * 16][kk],
                                       GBK + APADE);
#pragma unroll
            for (int j = 0; j < 4; j++)
                wmma::load_matrix_sync(bf[j], &Bs[sbuf][kk][wn0 + j * 16],
                                       GBN + BPADE);
#pragma unroll
            for (int i = 0; i < 2; i++)
#pragma unroll
                for (int j = 0; j < 4; j++)
                    wmma::mma_sync(acc[i][j], af[i], bf[j], acc[i][j]);
        }
        sbuf ^= 1;
    }
    __syncthreads();

    int r = lane >> 1;
    int cbase = (lane & 1) * 8;
#pragma unroll
    for (int i = 0; i < 2; i++) {
#pragma unroll
        for (int j = 0; j < 4; j++) {
            wmma::store_matrix_sync(&stage[wid][0][0], acc[i][j], 20,
                                    wmma::mem_row_major);
            __syncwarp();
            int grow = m0 + wm0 + i * 16 + r;
            int gcol = n0 + wn0 + j * 16 + cbase;
            if (MODE == 0) {
                if (grow < M) {
                    float4 v1 = *(const float4*)(&stage[wid][r][cbase]);
                    float4 v2 = *(const float4*)(&stage[wid][r][cbase + 4]);
                    float4 b1 = *(const float4*)(bias + gcol);
                    float4 b2 = *(const float4*)(bias + gcol + 4);
                    v1.x += b1.x; v1.y += b1.y; v1.z += b1.z; v1.w += b1.w;
                    v2.x += b2.x; v2.y += b2.y; v2.z += b2.z; v2.w += b2.w;
                    __nv_bfloat162 r0 = __floats2bfloat162_rn(v1.x, v1.y);
                    __nv_bfloat162 r1 = __floats2bfloat162_rn(v1.z, v1.w);
                    __nv_bfloat162 r2 = __floats2bfloat162_rn(v2.x, v2.y);
                    __nv_bfloat162 r3 = __floats2bfloat162_rn(v2.z, v2.w);
                    uint4 ov;
                    ov.x = *reinterpret_cast<unsigned*>(&r0);
                    ov.y = *reinterpret_cast<unsigned*>(&r1);
                    ov.z = *reinterpret_cast<unsigned*>(&r2);
                    ov.w = *reinterpret_cast<unsigned*>(&r3);
                    *(uint4*)((__nv_bfloat16*)Cv + (size_t)grow * DD + gcol) = ov;
                }
            } else {
                float t[8];
                if (grow < M) {
                    float4 v1 = *(const float4*)(&stage[wid][r][cbase]);
                    float4 v2 = *(const float4*)(&stage[wid][r][cbase + 4]);
                    float4 b1 = *(const float4*)(bias + gcol);
                    float4 b2 = *(const float4*)(bias + gcol + 4);
                    t[0] = tanha(v1.x + b1.x); t[1] = tanha(v1.y + b1.y);
                    t[2] = tanha(v1.z + b1.z); t[3] = tanha(v1.w + b1.w);
                    t[4] = tanha(v2.x + b2.x); t[5] = tanha(v2.y + b2.y);
                    t[6] = tanha(v2.z + b2.z); t[7] = tanha(v2.w + b2.w);
                } else {
#pragma unroll
                    for (int q = 0; q < 8; q++) t[q] = 0.f;
                }
#pragma unroll
                for (int d = 2; d <= 16; d <<= 1)
#pragma unroll
                    for (int q = 0; q < 8; q++)
                        t[q] += __shfl_xor_sync(0xffffffffu, t[q], d);
                if (lane < 2) {
                    int lc = wn0 + j * 16 + lane * 8;
#pragma unroll
                    for (int q = 0; q < 8; q++)
                        atomicAdd(&ksred[lc + q], t[q]);
                }
            }
            __syncwarp();
        }
    }
    if (MODE == 1) {
        __syncthreads();
        if (tid < GBN)
            atomicAdd(&ksum_out[bank * DD + n0 + tid], ksred[tid]);
    }
}

// ---------------- attention dots, att vectors staged in shared ---------------
__global__ void compute_ah3(const __nv_bfloat16* __restrict__ hmat,
                            const float* __restrict__ att0, float* __restrict__ a0,
                            const float* __restrict__ att1, float* __restrict__ a1,
                            const float* __restrict__ att2, float* __restrict__ a2,
                            int n_nodes) {
    __shared__ float s_att[3][DD];
    int tid = threadIdx.x;
    // cooperative att staging: 512 floats per vector, 256 threads -> 2 each
    {
        float4 v0 = ((const float4*)att0)[tid & 127];
        ((float4*)s_att[0])[tid & 127] = v0;
        if (att1) ((float4*)s_att[1])[tid & 127] = ((const float4*)att1)[tid & 127];
        if (att2) ((float4*)s_att[2])[tid & 127] = ((const float4*)att2)[tid & 127];
        (void)v0;
    }
    __syncthreads();

    int gt = blockIdx.x * blockDim.x + tid;
    int warp = gt >> 5;
    int lane = tid & 31;
    if (warp >= n_nodes) return;
    int base = lane * 16;
    const uint4* hp = (const uint4*)(hmat + (size_t)warp * DD + base);
    uint4 qa = hp[0], qb = hp[1];
    __nv_bfloat162* pa = reinterpret_cast<__nv_bfloat162*>(&qa);
    __nv_bfloat162* pb = reinterpret_cast<__nv_bfloat162*>(&qb);
    float hv[16];
#pragma unroll
    for (int j = 0; j < 4; j++) {
        float2 f = __bfloat1622float2(pa[j]);
        hv[2 * j] = f.x; hv[2 * j + 1] = f.y;
        float2 g = __bfloat1622float2(pb[j]);
        hv[8 + 2 * j] = g.x; hv[8 + 2 * j + 1] = g.y;
    }
    float s0 = 0.f, s1 = 0.f, s2 = 0.f;
#pragma unroll
    for (int q = 0; q < 4; q++) {
        float4 av = *(const float4*)(&s_att[0][base + q * 4]);
        s0 += hv[q*4]*av.x + hv[q*4+1]*av.y + hv[q*4+2]*av.z + hv[q*4+3]*av.w;
        if (att1) {
            float4 bv = *(const float4*)(&s_att[1][base + q * 4]);
            s1 += hv[q*4]*bv.x + hv[q*4+1]*bv.y + hv[q*4+2]*bv.z + hv[q*4+3]*bv.w;
        }
        if (att2) {
            float4 cv = *(const float4*)(&s_att[2][base + q * 4]);
            s2 += hv[q*4]*cv.x + hv[q*4+1]*cv.y + hv[q*4+2]*cv.z + hv[q*4+3]*cv.w;
        }
    }
#pragma unroll
    for (int d = 1; d <= 2; d <<= 1) {
        s0 += __shfl_xor_sync(0xffffffffu, s0, d);
        s1 += __shfl_xor_sync(0xffffffffu, s1, d);
        s2 += __shfl_xor_sync(0xffffffffu, s2, d);
    }
    if ((lane & 3) == 0) {
        int o = warp * HH + (lane >> 2);
        a0[o] = s0;
        if (a1) a1[o] = s1;
        if (a2) a2[o] = s2;
    }
}

// ---------------- edge pass 1 ------------------------------------------------
__global__ void edge_alpha_max2(
        const int* __restrict__ s0p, const int* __restrict__ d0p,
        const int* __restrict__ s1p, const int* __restrict__ d1p,
        const float* __restrict__ ase, const float* __restrict__ ade,
        const float* __restrict__ aso, const float* __restrict__ ado,
        float* __restrict__ alpha, unsigned* __restrict__ amax,
        int* __restrict__ deg, int ne) {
    int i = blockIdx.x * blockDim.x + threadIdx.x;
    int half = ne * HH;
    if (i >= 2 * half) return;
    int m = i >= half;
    int li = m ? i - half : i;
    int e = li >> 3, h = li & 7;
    const int* sp = m ? s1p : s0p;
    const int* dp = m ? d1p : d0p;
    const float* as = m ? aso : ase;
    const float* ad = m ? ado : ade;
    int d = dp[e];
    float v = as[sp[e] * HH + h] + ad[d * HH + h];
    v = (v > 0.f) ? v : 0.2f * v;
    alpha[i] = v;
    atomicMax(&amax[m * NN * HH + d * HH + h], mapf(v));
    if (h == 0) atomicAdd(&deg[m * NN + d], 1);
}

// ---------------- edge pass 2 ------------------------------------------------
__global__ void edge_exp_sum2(
        const int* __restrict__ d0p, const int* __restrict__ d1p,
        float* __restrict__ alpha, const unsigned* __restrict__ amax,
        float* __restrict__ denom, int ne) {
    int i = blockIdx.x * blockDim.x + threadIdx.x;
    int half = ne * HH;
    if (i >= 2 * half) return;
    int m = i >= half;
    int li = m ? i - half : i;
    int e = li >> 3, h = li & 7;
    const int* dp = m ? d1p : d0p;
    int off = m * NN * HH + dp[e] * HH + h;
    float ex = expf(alpha[i] - unmapf(amax[off]));
    alpha[i] = ex;
    atomicAdd(&denom[off], ex);
}

// ---------------- scans -------------------------------------------------------
__global__ void scan1(const int* __restrict__ vin, int* __restrict__ outv,
                      int* __restrict__ bsum, int n) {
    __shared__ int sh[1024];
    int gid = blockIdx.x * 1024 + threadIdx.x;
    int v = (gid < n) ? vin[gid] : 0;
    sh[threadIdx.x] = v;
    __syncthreads();
    for (int off = 1; off < 1024; off <<= 1) {
        int t = (threadIdx.x >= off) ? sh[threadIdx.x - off] : 0;
        __syncthreads();
        sh[threadIdx.x] += t;
        __syncthreads();
    }
    if (gid < n) outv[gid] = sh[threadIdx.x] - v;
    if (threadIdx.x == 1023) bsum[blockIdx.x] = sh[1023];
}

__global__ void scan2(int* __restrict__ bsum, int nb) {
    __shared__ int sh[256];
    int v = (threadIdx.x < nb) ? bsum[threadIdx.x] : 0;
    sh[threadIdx.x] = v;
    __syncthreads();
    for (int off = 1; off < 256; off <<= 1) {
        int t = (threadIdx.x >= off) ? sh[threadIdx.x - off] : 0;
        __syncthreads();
        sh[threadIdx.x] += t;
        __syncthreads();
    }
    if (threadIdx.x < nb) bsum[threadIdx.x] = sh[threadIdx.x] - v;
}

__global__ void scan3(int* __restrict__ outv, const int* __restrict__ bsum,
                      int n) {
    int gid = blockIdx.x * 1024 + threadIdx.x;
    if (gid < n) outv[gid] += bsum[blockIdx.x];
}

__global__ void make_ind(const int* __restrict__ deg, int* __restrict__ ind,
                         int n) {
    int i = blockIdx.x * blockDim.x + threadIdx.x;
    if (i < n) ind[i] = (deg[i] > 0) ? 1 : 0;
}

__global__ void meta_k(const int* __restrict__ nzpos,
                       const int* __restrict__ deg, int* __restrict__ meta) {
    int nz0 = nzpos[NN];
    int nztot = nzpos[2 * NN - 1] + ((deg[2 * NN - 1] > 0) ? 1 : 0);
    int P0 = (nz0 + 127) & ~127;
    int nz1 = nztot - nz0;
    meta[0] = nz0;
    meta[1] = P0;
    meta[2] = P0 + nz1;
    meta[3] = NN - nz1;
}

__global__ void zero_pad(const int* __restrict__ meta,
                         __nv_bfloat16* __restrict__ Agg) {
    int nz0 = meta[0], P0 = meta[1];
    long total = (long)(P0 - nz0) * DD;
    long base = (size_t)nz0 * DD;
    for (long t = (long)blockIdx.x * blockDim.x + threadIdx.x; t < total;
         t += (long)gridDim.x * blockDim.x)
        Agg[base + t] = __float2bfloat16(0.f);
}

__global__ void csr_fill(
        const int* __restrict__ s0p, const int* __restrict__ d0p,
        const int* __restrict__ s1p, const int* __restrict__ d1p,
        const int* __restrict__ startv, int* __restrict__ cur,
        int* __restrict__ eidx, int* __restrict__ esrc, int ne) {
    int i = blockIdx.x * blockDim.x + threadIdx.x;
    if (i >= 2 * ne) return;
    int m = i >= ne;
    int le = m ? i - ne : i;
    int d = m ? d1p[le] : d0p[le];
    int s = m ? s1p[le] : s0p[le];
    int dd = m * NN + d;
    int pos = startv[dd] + atomicAdd(&cur[dd], 1);
    eidx[pos] = i;
    esrc[pos] = s;
}

// ---------------- gather -> compacted Agg ------------------------------------
__global__ void gather_conv(
        const int* __restrict__ eidx, const int* __restrict__ esrc,
        const int* __restrict__ startv, const int* __restrict__ deg,
        const int* __restrict__ nzpos, const int* __restrict__ meta,
        const __nv_bfloat16* __restrict__ h0,
        const __nv_bfloat16* __restrict__ h1,
        const float* __restrict__ ebuf, const float* __restrict__ denom,
        __nv_bfloat16* __restrict__ Agg) {
    int gw = (blockIdx.x * blockDim.x + threadIdx.x) >> 5;
    int lane = threadIdx.x & 31;
    if (gw >= 2 * NN) return;
    int de = deg[gw];
    if (de == 0) return;
    int m = gw >= NN;
    const __nv_bfloat16* hs = m ? h1 : h0;
    int row = m ? (meta[1] + nzpos[gw] - meta[0]) : nzpos[gw];
    int st = startv[gw];
    int h = lane >> 2;
    float dinv = 1.0f / (denom[gw * HH + h] + 1e-16f);
    float acc[16];
#pragma unroll
    for (int q = 0; q < 16; q++) acc[q] = 0.f;

    for (int p = 0; p < de; p++) {
        int ge = eidx[st + p];
        int s  = esrc[st + p];
        float w = ebuf[ge * HH + h] * dinv;
        const uint4* hp = (const uint4*)(hs + (size_t)s * DD + lane * 16);
        uint4 qa = hp[0], qb = hp[1];
        __nv_bfloat162* pa = reinterpret_cast<__nv_bfloat162*>(&qa);
        __nv_bfloat162* pb = reinterpret_cast<__nv_bfloat162*>(&qb);
#pragma unroll
        for (int j = 0; j < 4; j++) {
            float2 f = __bfloat1622float2(pa[j]);
            acc[2 * j]     += f.x * w;
            acc[2 * j + 1] += f.y * w;
            float2 g = __bfloat1622float2(pb[j]);
            acc[8 + 2 * j]     += g.x * w;
            acc[8 + 2 * j + 1] += g.y * w;
        }
    }

    uint4 o1, o2;
#pragma unroll
    for (int j = 0; j < 8; j++) {
        float a = fmaxf(acc[2 * j], 0.f);
        float b = fmaxf(acc[2 * j + 1], 0.f);
        __nv_bfloat162 pk = __floats2bfloat162_rn(a, b);
        if (j < 4) (&o1.x)[j] = *reinterpret_cast<unsigned*>(&pk);
        else       (&o2.x)[j - 4] = *reinterpret_cast<unsigned*>(&pk);
    }
    uint4* dst = (uint4*)(Agg + (size_t)row * DD + lane * 16);
    dst[0] = o1;
    dst[1] = o2;
}

// ---------------- final -------------------------------------------------------
__global__ void final_kernel(const float* __restrict__ qsem,
                             const float* __restrict__ klb,
                             const float* __restrict__ linw,
                             const float* __restrict__ linb,
                             const int* __restrict__ meta,
                             float* __restrict__ out) {
    __shared__ float sh[DD];
    __shared__ float sv[2];
    int f = threadIdx.x;
    const float invN = 1.0f / (float)NN;
    float q = qsem[f];
    float tb = tanhf(klb[f]);
    float c0 = (float)(NN - meta[1]);
    float c1 = (float)meta[3];
    float v0 = (g_ksum[f] + c0 * tb) * invN * q;
    float v1 = (g_ksum[DD + f] + c1 * tb) * invN * q;

    sh[f] = v0; __syncthreads();
    for (int s = 256; s > 0; s >>= 1) { if (f < s) sh[f] += sh[f + s]; __syncthreads(); }
    if (f == 0) sv[0] = sh[0];
    __syncthreads();
    sh[f] = v1; __syncthreads();
    for (int s = 256; s > 0; s >>= 1) { if (f < s) sh[f] += sh[f + s]; __syncthreads(); }
    if (f == 0) sv[1] = sh[0];
    __syncthreads();

    float s0 = sv[0], s1 = sv[1];
    float mx = fmaxf(s0, s1);
    float e0 = expf(s0 - mx), e1 = expf(s1 - mx);
    float sem0 = e0 / (e0 + e1), sem1 = e1 / (e0 + e1);

    float pooled = (sem0 * g_musum[f] + sem1 * g_musum[DD + f]) * invN;
    float w0 = pooled * linw[f * 2 + 0];
    float w1 = pooled * linw[f * 2 + 1];

    sh[f] = w0; __syncthreads();
    for (int s = 256; s > 0; s >>= 1) { if (f < s) sh[f] += sh[f + s]; __syncthreads(); }
    if (f == 0) out[0] = sh[0] + linb[0];
    __syncthreads();
    sh[f] = w1; __syncthreads();
    for (int s = 256; s > 0; s >>= 1) { if (f < s) sh[f] += sh[f + s]; __syncthreads(); }
    if (f == 0) out[1] = sh[0] + linb[1];
}

// ---------------- host launcher ---------------------------------------------
extern "C" void kernel_launch(void* const* d_in, const int* in_sizes, int n_in,
                              void* d_out, int out_size) {
    const float* x_o  = (const float*)d_in[0];
    const float* x_e  = (const float*)d_in[1];
    const int*   e2o  = (const int*)d_in[2];
    const int*   o2o  = (const int*)d_in[3];
    const float* powm = (const float*)d_in[4];
    const float* pob  = (const float*)d_in[5];
    const float* pewm = (const float*)d_in[6];
    const float* peb  = (const float*)d_in[7];
    const float* a_s_e2o = (const float*)d_in[8];
    const float* a_d_e2o = (const float*)d_in[9];
    const float* a_s_o2o = (const float*)d_in[10];
    const float* a_d_o2o = (const float*)d_in[11];
    const float* klw  = (const float*)d_in[12];
    const float* klb  = (const float*)d_in[13];
    const float* qsem = (const float*)d_in[14];
    const float* linw = (const float*)d_in[15];
    const float* linb = (const float*)d_in[16];
    float* out = (float*)d_out;

    void* p;
    float *a_se, *a_de, *a_so, *a_do, *denom, *ebuf, *ksum, *musum;
    __nv_bfloat16 *hb_o, *hb_e, *Ab, *Agg, *Wb;
    unsigned* amax;
    int *deg, *cur, *startv, *ind, *nzpos, *bsum, *bsum2, *meta, *eidx, *esrc;
    cudaGetSymbolAddress(&p, g_hb_o); hb_o = (__nv_bfloat16*)p;
    cudaGetSymbolAddress(&p, g_hb_e); hb_e = (__nv_bfloat16*)p;
    cudaGetSymbolAddress(&p, g_Ab);   Ab   = (__nv_bfloat16*)p;
    cudaGetSymbolAddress(&p, g_Agg);  Agg  = (__nv_bfloat16*)p;
    cudaGetSymbolAddress(&p, g_Wb);   Wb   = (__nv_bfloat16*)p;
    cudaGetSymbolAddress(&p, g_a_se); a_se = (float*)p;
    cudaGetSymbolAddress(&p, g_a_de); a_de = (float*)p;
    cudaGetSymbolAddress(&p, g_a_so); a_so = (float*)p;
    cudaGetSymbolAddress(&p, g_a_do); a_do = (float*)p;
    cudaGetSymbolAddress(&p, g_amax); amax = (unsigned*)p;
    cudaGetSymbolAddress(&p, g_denom); denom = (float*)p;
    cudaGetSymbolAddress(&p, g_ebuf); ebuf = (float*)p;
    cudaGetSymbolAddress(&p, g_deg);  deg  = (int*)p;
    cudaGetSymbolAddress(&p, g_cur);  cur  = (int*)p;
    cudaGetSymbolAddress(&p, g_startArr); startv = (int*)p;
    cudaGetSymbolAddress(&p, g_ind);  ind  = (int*)p;
    cudaGetSymbolAddress(&p, g_nzpos); nzpos = (int*)p;
    cudaGetSymbolAddress(&p, g_bsum); bsum = (int*)p;
    cudaGetSymbolAddress(&p, g_bsum2); bsum2 = (int*)p;
    cudaGetSymbolAddress(&p, g_meta); meta = (int*)p;
    cudaGetSymbolAddress(&p, g_eidx); eidx = (int*)p;
    cudaGetSymbolAddress(&p, g_esrc); esrc = (int*)p;
    cudaGetSymbolAddress(&p, g_ksum); ksum = (float*)p;
    cudaGetSymbolAddress(&p, g_musum); musum = (float*)p;

    const long ND = (long)NN * DD;
    dim3 tcgrid(DD / GBN, (NN + GBM - 1) / GBM);
    dim3 tcgrid2(DD / GBN, (2 * NN + GBM - 1) / GBM);
    const int NTOT = 2 * NN;
    const int SCAN_BLOCKS = (NTOT + 1023) / 1024;

    // ---- GEMM 1 as launch #4 (ncu capture point) ----
    conv_bf<<<256, 256>>>(powm, Wb, DD * DD);
    conv_bf<<<2048, 256>>>(x_o, Ab, ND);
    zero_buf<<<4, 256>>>(ksum, 2 * DD);
    gemm_bf<0><<<tcgrid, 256>>>(Ab, Wb, pob, hb_o, NN, nullptr, nullptr);

    zero_buf<<<4, 256>>>(musum, 2 * DD);

    // ---- GEMM 2 ----
    conv_bf<<<256, 256>>>(pewm, Wb, DD * DD);
    conv_bf<<<2048, 256>>>(x_e, Ab, ND);
    gemm_bf<0><<<tcgrid, 256>>>(Ab, Wb, peb, hb_e, NN, nullptr, nullptr);

    int ah_blocks = (NN * 32 + 255) / 256;
    int e2_blocks = (2 * EE * HH + 255) / 256;
    int ef_blocks = (2 * EE + 255) / 256;
    int ie_blocks = (2 * NN * HH + 255) / 256;
    int gw_blocks = (2 * NN * 32 + 255) / 256;

    // ---- attention dots (att staged in shared) ----
    compute_ah3<<<ah_blocks, 256>>>(hb_o, a_d_e2o, a_de, a_s_o2o, a_so, a_d_o2o, a_do, NN);
    compute_ah3<<<ah_blocks, 256>>>(hb_e, a_s_e2o, a_se, nullptr, nullptr, nullptr, nullptr, NN);

    // ---- edge passes ----
    init_edge_state2<<<ie_blocks, 256>>>(amax, denom, deg, cur, 2 * NN * HH);
    edge_alpha_max2<<<e2_blocks, 256>>>(e2o, e2o + EE, o2o, o2o + EE,
                                        a_se, a_de, a_so, a_do, ebuf, amax, deg, EE);
    edge_exp_sum2<<<e2_blocks, 256>>>(e2o + EE, o2o + EE, ebuf, amax, denom, EE);

    // ---- CSR scan + nonzero-compaction scan ----
    scan1<<<SCAN_BLOCKS, 1024>>>(deg, startv, bsum, NTOT);
    scan2<<<1, 256>>>(bsum, SCAN_BLOCKS);
    scan3<<<SCAN_BLOCKS, 1024>>>(startv, bsum, NTOT);
    make_ind<<<(NTOT + 255) / 256, 256>>>(deg, ind, NTOT);
    scan1<<<SCAN_BLOCKS, 1024>>>(ind, nzpos, bsum2, NTOT);
    scan2<<<1, 256>>>(bsum2, SCAN_BLOCKS);
    scan3<<<SCAN_BLOCKS, 1024>>>(nzpos, bsum2, NTOT);
    meta_k<<<1, 1>>>(nzpos, deg, meta);
    csr_fill<<<ef_blocks, 256>>>(e2o, e2o + EE, o2o, o2o + EE,
                                 startv, cur, eidx, esrc, EE);
    zero_pad<<<128, 256>>>(meta, Agg);

    // ---- gather -> compacted Agg ----
    gather_conv<<<gw_blocks, 256>>>(eidx, esrc, startv, deg, nzpos, meta,
                                    hb_e, hb_o, ebuf, denom, Agg);

    // ---- semantic attention on compacted rows ----
    conv_bf<<<256, 256>>>(klw, Wb, DD * DD);
    mu_bf2<<<256, 512>>>(Agg, musum, meta);
    gemm_bf<1><<<tcgrid2, 256>>>(Agg, Wb, klb, nullptr, 2 * NN, ksum, meta);

    // ---- corrections + softmax + pool + linear ----
    final_kernel<<<1, 512>>>(qsem, klb, linw, linb, meta, out);
}